// round 1
// baseline (speedup 1.0000x reference)
#include <cuda_runtime.h>
#include <cstdint>

// ---------------- problem constants ----------------
constexpr int B    = 2048;
constexpr int S    = 24;
constexpr int T    = 25;
constexpr int H    = 256;
constexpr int E    = 300;
constexpr int VOUTD= 128;
constexpr int H3   = 3 * H;      // 768
constexpr int DH   = 2 * H;      // 512
constexpr int XG   = E + DH;     // 812  (emb, weighted)
constexpr int CATD = H + DH + E; // 1068 (hn, weighted, emb)

// ---------------- scratch (static device, no allocation) ----------------
__device__ float d_x     [S * B * E];        // encoder embeddings
__device__ float d_gi_f  [S * B * H3];       // precomputed x@Wih_f + bih_f
__device__ float d_gi_b  [S * B * H3];
__device__ float d_h2    [2 * B * H];        // fwd/bwd hidden states
__device__ float d_gh2   [2 * B * H3];       // fwd/bwd h@Whh
__device__ float d_encbse[B * S * DH];       // enc outputs, (B,S,2H)
__device__ float d_hcat  [B * DH];
__device__ float d_hid   [B * H];            // decoder hidden
__device__ float d_eproj [B * S * H];        // enc_bse @ attn_We
__device__ float d_embseq[(T - 1) * B * E];  // decoder input embeddings
__device__ float d_q     [B * H];
__device__ float d_sc    [B * S];            // attention scores
__device__ float d_xg    [B * XG];           // decoder GRU input concat
__device__ float d_cat   [B * CATD];         // logits input concat
__device__ float d_gid   [B * H3];
__device__ float d_ghd   [B * H3];

// ---------------- helpers ----------------
__device__ __forceinline__ float sigmoidf(float x) { return 1.f / (1.f + expf(-x)); }

struct GA {
    const float* A;     // M x K, row-major, lda = K
    const float* W;     // K x N, row-major, ldb = N
    const float* bias;  // N or nullptr
    float*       C;     // M x N, ldc = N
    int M, N, K;
    int act;            // 0 = none, 1 = tanh
};

// 64x64x16 tile, 256 threads, 4x4 register blocking, float4 smem traffic.
__device__ __forceinline__ void gemm_body(const GA g) {
    constexpr int BM = 64, BN = 64, BK = 16;
    __shared__ __align__(16) float As[BK][BM];  // transposed A tile
    __shared__ __align__(16) float Bs[BK][BN];

    const int tid = threadIdx.x;
    const int tx  = tid & 15;   // col group
    const int ty  = tid >> 4;   // row group
    const int row0 = blockIdx.y * BM;
    const int col0 = blockIdx.x * BN;
    if (row0 >= g.M || col0 >= g.N) return;

    float acc[4][4] = {};

    for (int k0 = 0; k0 < g.K; k0 += BK) {
        // ---- load A tile (64 x 16), one float4 per thread ----
        {
            const int r  = tid >> 2;          // 0..63
            const int c4 = (tid & 3) * 4;     // 0,4,8,12
            const int gr = row0 + r;
            float4 v;
            if (k0 + BK <= g.K && gr < g.M) {
                v = *reinterpret_cast<const float4*>(&g.A[(size_t)gr * g.K + k0 + c4]);
            } else {
                float t[4];
                #pragma unroll
                for (int u = 0; u < 4; u++) {
                    int gc = k0 + c4 + u;
                    t[u] = (gr < g.M && gc < g.K) ? g.A[(size_t)gr * g.K + gc] : 0.f;
                }
                v = make_float4(t[0], t[1], t[2], t[3]);
            }
            As[c4 + 0][r] = v.x; As[c4 + 1][r] = v.y;
            As[c4 + 2][r] = v.z; As[c4 + 3][r] = v.w;
        }
        // ---- load B tile (16 x 64), one float4 per thread ----
        {
            const int r  = tid >> 4;          // 0..15
            const int c4 = (tid & 15) * 4;    // 0..60
            const int gr = k0 + r;
            float4 v;
            if (gr < g.K) {
                v = *reinterpret_cast<const float4*>(&g.W[(size_t)gr * g.N + col0 + c4]);
            } else {
                v = make_float4(0.f, 0.f, 0.f, 0.f);
            }
            *reinterpret_cast<float4*>(&Bs[r][c4]) = v;
        }
        __syncthreads();

        #pragma unroll
        for (int kk = 0; kk < BK; kk++) {
            float4 a = *reinterpret_cast<const float4*>(&As[kk][ty * 4]);
            float4 b = *reinterpret_cast<const float4*>(&Bs[kk][tx * 4]);
            float av[4] = {a.x, a.y, a.z, a.w};
            float bv[4] = {b.x, b.y, b.z, b.w};
            #pragma unroll
            for (int i = 0; i < 4; i++)
                #pragma unroll
                for (int j = 0; j < 4; j++)
                    acc[i][j] += av[i] * bv[j];
        }
        __syncthreads();
    }

    #pragma unroll
    for (int i = 0; i < 4; i++) {
        const int r = row0 + ty * 4 + i;
        if (r >= g.M) continue;
        #pragma unroll
        for (int j = 0; j < 4; j++) {
            const int c = col0 + tx * 4 + j;
            if (c >= g.N) continue;
            float v = acc[i][j] + (g.bias ? g.bias[c] : 0.f);
            if (g.act == 1) v = tanhf(v);
            g.C[(size_t)r * g.N + c] = v;
        }
    }
}

__global__ void gemm1(GA g) { gemm_body(g); }
__global__ void gemm2(GA g0, GA g1) { gemm_body(blockIdx.z ? g1 : g0); }

// ---------------- elementwise / gather kernels ----------------
__global__ void zero_kernel(float* p, int n) {
    int i = blockIdx.x * blockDim.x + threadIdx.x;
    if (i < n) p[i] = 0.f;
}

__global__ void embed_kernel(const int* __restrict__ idx, const float* __restrict__ emb,
                             float* __restrict__ out, int n_tok) {
    int i = blockIdx.x * blockDim.x + threadIdx.x;
    if (i >= n_tok * E) return;
    int tok = i / E, e = i - tok * E;
    out[i] = emb[idx[tok] * E + e];
}

// encoder GRU gate (both directions), writes new h and enc_bse
__global__ void enc_gate_kernel(int t) {
    int i = blockIdx.x * blockDim.x + threadIdx.x;
    if (i >= 2 * B * H) return;
    int dir = i / (B * H);
    int rem = i - dir * (B * H);
    int b = rem / H, j = rem - b * H;

    int gi_row = dir ? (S - 1 - t) : t;
    const float* gi = (dir ? d_gi_b : d_gi_f) + ((size_t)gi_row * B + b) * H3;
    const float* gh = d_gh2 + ((size_t)dir * B + b) * H3;

    float h  = d_h2[i];
    float r  = sigmoidf(gi[j]         + gh[j]);
    float z  = sigmoidf(gi[j + H]     + gh[j + H]);
    float n  = tanhf  (gi[j + 2 * H] + r * gh[j + 2 * H]);
    float hn = (1.f - z) * n + z * h;
    d_h2[i] = hn;

    int s_out = dir ? (S - 1 - t) : t;
    d_encbse[((size_t)b * S + s_out) * DH + dir * H + j] = hn;
}

__global__ void hcat_kernel() {
    int i = blockIdx.x * blockDim.x + threadIdx.x;
    if (i >= B * DH) return;
    int b = i / DH, j = i - b * DH;
    d_hcat[i] = d_h2[(j < H ? 0 : 1) * B * H + b * H + (j & (H - 1))];
}

// attention energy: scores[b,s] = sum_k tanh(q[b,k]+eproj[b,s,k]+ab[k]) * v[k]
__global__ void energy_kernel(const float* __restrict__ ab, const float* __restrict__ v) {
    int gw   = (blockIdx.x * blockDim.x + threadIdx.x) >> 5;
    int lane = threadIdx.x & 31;
    if (gw >= B * S) return;
    int b = gw / S, s = gw - b * S;
    const float* ep = d_eproj + ((size_t)b * S + s) * H;
    const float* q  = d_q + (size_t)b * H;
    float acc = 0.f;
    #pragma unroll 4
    for (int k = lane; k < H; k += 32)
        acc += tanhf(q[k] + ep[k] + ab[k]) * v[k];
    #pragma unroll
    for (int o = 16; o; o >>= 1) acc += __shfl_down_sync(0xFFFFFFFFu, acc, o);
    if (lane == 0) d_sc[b * S + s] = acc;
}

// softmax over S per batch row + weighted sum -> xg[:,E:] and cat[:,H:H+DH]
__global__ void softmax_weighted_kernel() {
    int b = blockIdx.x;
    __shared__ float a[S];
    if (threadIdx.x == 0) {
        float m = -1e30f;
        #pragma unroll
        for (int s = 0; s < S; s++) m = fmaxf(m, d_sc[b * S + s]);
        float sum = 0.f;
        #pragma unroll
        for (int s = 0; s < S; s++) { float ex = expf(d_sc[b * S + s] - m); a[s] = ex; sum += ex; }
        float inv = 1.f / sum;
        #pragma unroll
        for (int s = 0; s < S; s++) a[s] *= inv;
    }
    __syncthreads();
    for (int d = threadIdx.x; d < DH; d += blockDim.x) {
        const float* eb = d_encbse + (size_t)b * S * DH + d;
        float w = 0.f;
        #pragma unroll
        for (int s = 0; s < S; s++) w += a[s] * eb[s * DH];
        d_xg [b * XG   + E + d] = w;
        d_cat[b * CATD + H + d] = w;
    }
}

// copy decoder embedding for step t into xg[:,0:E] and cat[:,H+DH:]
__global__ void dec_prep_kernel(int t) {
    int i = blockIdx.x * blockDim.x + threadIdx.x;
    if (i >= B * E) return;
    int b = i / E, e = i - b * E;
    float v = d_embseq[(size_t)t * B * E + i];
    d_xg [b * XG + e]           = v;
    d_cat[b * CATD + H + DH + e] = v;
}

__global__ void dec_gate_kernel() {
    int i = blockIdx.x * blockDim.x + threadIdx.x;
    if (i >= B * H) return;
    int b = i / H, j = i - b * H;
    const float* gi = d_gid + (size_t)b * H3;
    const float* gh = d_ghd + (size_t)b * H3;
    float h  = d_hid[i];
    float r  = sigmoidf(gi[j]         + gh[j]);
    float z  = sigmoidf(gi[j + H]     + gh[j + H]);
    float n  = tanhf  (gi[j + 2 * H] + r * gh[j + 2 * H]);
    float hn = (1.f - z) * n + z * h;
    d_hid[i] = hn;
    d_cat[b * CATD + j] = hn;
}

// ---------------- host ----------------
static float* sym_addr(const void* symbol) {
    void* p = nullptr;
    cudaGetSymbolAddress(&p, symbol);
    return (float*)p;
}

extern "C" void kernel_launch(void* const* d_in, const int* in_sizes, int n_in,
                              void* d_out, int out_size) {
    const int*   src    = (const int*)  d_in[0];
    const int*   trg    = (const int*)  d_in[1];
    const float* eemb   = (const float*)d_in[2];
    const float* Wih_f  = (const float*)d_in[3];
    const float* Whh_f  = (const float*)d_in[4];
    const float* bih_f  = (const float*)d_in[5];
    const float* bhh_f  = (const float*)d_in[6];
    const float* Wih_b  = (const float*)d_in[7];
    const float* Whh_b  = (const float*)d_in[8];
    const float* bih_b  = (const float*)d_in[9];
    const float* bhh_b  = (const float*)d_in[10];
    const float* efcW   = (const float*)d_in[11];
    const float* efcb   = (const float*)d_in[12];
    const float* aWh    = (const float*)d_in[13];
    const float* aWe    = (const float*)d_in[14];
    const float* ab     = (const float*)d_in[15];
    const float* av     = (const float*)d_in[16];
    const float* demb   = (const float*)d_in[17];
    const float* dWih   = (const float*)d_in[18];
    const float* dWhh   = (const float*)d_in[19];
    const float* dbih   = (const float*)d_in[20];
    const float* dbhh   = (const float*)d_in[21];
    const float* fcW    = (const float*)d_in[22];
    const float* fcb    = (const float*)d_in[23];
    float* out = (float*)d_out;

    float* px      = sym_addr(d_x);
    float* pgi_f   = sym_addr(d_gi_f);
    float* pgi_b   = sym_addr(d_gi_b);
    float* ph2     = sym_addr(d_h2);
    float* pgh2    = sym_addr(d_gh2);
    float* pencbse = sym_addr(d_encbse);
    float* phcat   = sym_addr(d_hcat);
    float* phid    = sym_addr(d_hid);
    float* peproj  = sym_addr(d_eproj);
    float* pembseq = sym_addr(d_embseq);
    float* pq      = sym_addr(d_q);
    float* pxg     = sym_addr(d_xg);
    float* pcat    = sym_addr(d_cat);
    float* pgid    = sym_addr(d_gid);
    float* pghd    = sym_addr(d_ghd);

    auto cdiv = [](int a, int b) { return (a + b - 1) / b; };

    // init: h0 = 0 (both directions), outputs[0] = 0
    zero_kernel<<<cdiv(2 * B * H, 256), 256>>>(ph2, 2 * B * H);
    zero_kernel<<<cdiv(B * VOUTD, 256), 256>>>(out, B * VOUTD);

    // embeddings
    embed_kernel<<<cdiv(S * B * E, 256), 256>>>(src, eemb, px, S * B);
    embed_kernel<<<cdiv((T - 1) * B * E, 256), 256>>>(trg, demb, pembseq, (T - 1) * B * E / E);

    // precompute all encoder input projections (both directions, fused)
    {
        GA g0{px, Wih_f, bih_f, pgi_f, S * B, H3, E, 0};
        GA g1{px, Wih_b, bih_b, pgi_b, S * B, H3, E, 0};
        dim3 gr(cdiv(H3, 64), cdiv(S * B, 64), 2);
        gemm2<<<gr, 256>>>(g0, g1);
    }

    // encoder recurrent scan (fwd + bwd fused per step)
    for (int t = 0; t < S; t++) {
        GA g0{ph2,           Whh_f, bhh_f, pgh2,           B, H3, H, 0};
        GA g1{ph2 + B * H,   Whh_b, bhh_b, pgh2 + B * H3,  B, H3, H, 0};
        dim3 gr(cdiv(H3, 64), cdiv(B, 64), 2);
        gemm2<<<gr, 256>>>(g0, g1);
        enc_gate_kernel<<<cdiv(2 * B * H, 256), 256>>>(t);
    }

    // decoder initial hidden = tanh([hf,hb] @ enc_fcW + b)
    hcat_kernel<<<cdiv(B * DH, 256), 256>>>();
    {
        GA g{phcat, efcW, efcb, phid, B, H, DH, 1};
        dim3 gr(cdiv(H, 64), cdiv(B, 64), 1);
        gemm1<<<gr, 256>>>(g);
    }

    // enc_proj = enc_bse @ attn_We
    {
        GA g{pencbse, aWe, nullptr, peproj, B * S, H, DH, 0};
        dim3 gr(cdiv(H, 64), cdiv(B * S, 64), 1);
        gemm1<<<gr, 256>>>(g);
    }

    // decoder scan
    for (int t = 0; t < T - 1; t++) {
        {   // q = h @ attn_Wh
            GA g{phid, aWh, nullptr, pq, B, H, H, 0};
            dim3 gr(cdiv(H, 64), cdiv(B, 64), 1);
            gemm1<<<gr, 256>>>(g);
        }
        energy_kernel<<<cdiv(B * S * 32, 128), 128>>>(ab, av);
        softmax_weighted_kernel<<<B, 256>>>();
        dec_prep_kernel<<<cdiv(B * E, 256), 256>>>(t);
        {   // gi = xg @ dec_Wih + bih ; gh = h @ dec_Whh + bhh (fused)
            GA g0{pxg,  dWih, dbih, pgid, B, H3, XG, 0};
            GA g1{phid, dWhh, dbhh, pghd, B, H3, H,  0};
            dim3 gr(cdiv(H3, 64), cdiv(B, 64), 2);
            gemm2<<<gr, 256>>>(g0, g1);
        }
        dec_gate_kernel<<<cdiv(B * H, 256), 256>>>();
        {   // logits = [hn, weighted, emb] @ fcW + fcb -> outputs[t+1]
            GA g{pcat, fcW, fcb, out + (size_t)(t + 1) * B * VOUTD, B, VOUTD, CATD, 0};
            dim3 gr(cdiv(VOUTD, 64), cdiv(B, 64), 1);
            gemm1<<<gr, 256>>>(g);
        }
    }
}

// round 6
// speedup vs baseline: 1.4517x; 1.4517x over previous
#include <cuda_runtime.h>
#include <cstdint>

// ---------------- problem constants ----------------
constexpr int B    = 2048;
constexpr int S    = 24;
constexpr int T    = 25;
constexpr int H    = 256;
constexpr int E    = 300;
constexpr int VIN  = 300;
constexpr int VOUTD= 128;
constexpr int H3   = 3 * H;      // 768
constexpr int DH   = 2 * H;      // 512
constexpr int CATK = H + DH;     // 768 (hn | weighted)
constexpr int GHQ  = H3 + H;     // 1024 (gh | q)

// ---------------- scratch (static device, no allocation) ----------------
__device__ float d_tabF [VIN * H3];          // emb @ Wih_f + bih_f
__device__ float d_tabB [VIN * H3];
__device__ float d_tabGi[VOUTD * H3];        // dec_emb @ dec_Wih[0:E]
__device__ float d_tabLg[VOUTD * VOUTD];     // dec_emb @ fcW[H+2H:]
__device__ float d_h2   [2 * B * H];         // fwd/bwd encoder hidden
__device__ float d_gh2  [2 * B * H3];        // h @ Whh (+bhh)
__device__ float d_encbse[B * S * DH];       // (B,S,2H)
__device__ float d_hcat [B * DH];
__device__ float d_hid  [B * H];             // decoder hidden
__device__ float d_eproj[B * S * H];
__device__ float d_w    [B * DH];            // attention-weighted context
__device__ float d_cat  [B * CATK];          // [hn | weighted]
__device__ float d_gi   [B * H3];
__device__ float d_ghq  [B * GHQ];           // [gh(768) | q(256)]
__device__ float d_Wghq [H * GHQ];           // [dWhh | attn_Wh]
__device__ float d_bghq [GHQ];               // [dbhh | 0]

__device__ __forceinline__ float sigmoidf(float x) { return 1.f / (1.f + expf(-x)); }

// ---------------- GEMM ----------------
struct GA {
    const float* A;     // M x K (lda=K)
    const float* W;     // K x N (ldb=N)
    const float* bias;  // N or null
    const float* gadd;  // gather-add table (rows of width N) or null
    const int*   gidx;  // per-row index or null
    float*       C;     // M x N
    int M, N, K;
    int act;            // 0 none, 1 tanh
};

// 128x64x16 tile, 256 threads, 8x4 per-thread, double-buffered smem.
template<int BM, int BN>
__device__ __forceinline__ void gemm_body(const GA g) {
    constexpr int BK  = 16;
    constexpr int TM  = BM / 16;
    constexpr int TN  = BN / 16;
    constexpr int PAD = 4;
    constexpr int AV  = BM / 64;   // float4 A loads per thread
    constexpr int BV  = BN / 64;

    __shared__ __align__(16) float As[2][BK][BM + PAD];
    __shared__ __align__(16) float Bs[2][BK][BN];

    const int tid  = threadIdx.x;
    const int tcol = tid & 15;
    const int trow = tid >> 4;
    const int row0 = blockIdx.y * BM;
    const int col0 = blockIdx.x * BN;
    if (row0 >= g.M || col0 >= g.N) return;

    const int nk = (g.K + BK - 1) / BK;
    float4 pa[AV], pb[BV];

    auto loadA = [&](int kt) {
        const int k0 = kt * BK;
        #pragma unroll
        for (int i = 0; i < AV; i++) {
            int idx = tid + i * 256;
            int rr  = idx >> 2;
            int c4  = (idx & 3) * 4;
            int gr  = row0 + rr, gc = k0 + c4;
            if (gr < g.M && gc < g.K)   // K % 4 == 0 for all call sites
                pa[i] = *reinterpret_cast<const float4*>(&g.A[(size_t)gr * g.K + gc]);
            else
                pa[i] = make_float4(0.f, 0.f, 0.f, 0.f);
        }
    };
    auto loadB = [&](int kt) {
        const int k0 = kt * BK;
        #pragma unroll
        for (int i = 0; i < BV; i++) {
            int idx = tid + i * 256;
            int rr  = idx / (BN / 4);
            int c4  = (idx % (BN / 4)) * 4;
            int gr  = k0 + rr;
            if (gr < g.K)
                pb[i] = *reinterpret_cast<const float4*>(&g.W[(size_t)gr * g.N + col0 + c4]);
            else
                pb[i] = make_float4(0.f, 0.f, 0.f, 0.f);
        }
    };
    auto stage = [&](int buf) {
        #pragma unroll
        for (int i = 0; i < AV; i++) {
            int idx = tid + i * 256;
            int rr  = idx >> 2;
            int c4  = (idx & 3) * 4;
            As[buf][c4 + 0][rr] = pa[i].x;
            As[buf][c4 + 1][rr] = pa[i].y;
            As[buf][c4 + 2][rr] = pa[i].z;
            As[buf][c4 + 3][rr] = pa[i].w;
        }
        #pragma unroll
        for (int i = 0; i < BV; i++) {
            int idx = tid + i * 256;
            int rr  = idx / (BN / 4);
            int c4  = (idx % (BN / 4)) * 4;
            *reinterpret_cast<float4*>(&Bs[buf][rr][c4]) = pb[i];
        }
    };

    float acc[TM][TN] = {};

    loadA(0); loadB(0);
    stage(0);
    __syncthreads();

    for (int kt = 0; kt < nk; kt++) {
        const int cur = kt & 1;
        if (kt + 1 < nk) { loadA(kt + 1); loadB(kt + 1); }
        #pragma unroll
        for (int kk = 0; kk < BK; kk++) {
            float a[TM], b[TN];
            #pragma unroll
            for (int i = 0; i < TM; i++) a[i] = As[cur][kk][trow * TM + i];
            #pragma unroll
            for (int j = 0; j < TN; j++) b[j] = Bs[cur][kk][tcol * TN + j];
            #pragma unroll
            for (int i = 0; i < TM; i++)
                #pragma unroll
                for (int j = 0; j < TN; j++)
                    acc[i][j] += a[i] * b[j];
        }
        if (kt + 1 < nk) { stage(cur ^ 1); __syncthreads(); }
    }

    #pragma unroll
    for (int i = 0; i < TM; i++) {
        const int r = row0 + trow * TM + i;
        if (r >= g.M) continue;
        const float* grow = g.gidx ? &g.gadd[(size_t)g.gidx[r] * g.N] : nullptr;
        #pragma unroll
        for (int j = 0; j < TN; j++) {
            const int c = col0 + tcol * TN + j;
            float v = acc[i][j];
            if (g.bias) v += g.bias[c];
            if (grow)   v += grow[c];
            if (g.act == 1) v = tanhf(v);
            g.C[(size_t)r * g.N + c] = v;
        }
    }
}

__global__ void __launch_bounds__(256) gemm1(GA g)          { gemm_body<128, 64>(g); }
__global__ void __launch_bounds__(256) gemm2(GA g0, GA g1)  { gemm_body<128, 64>(blockIdx.z ? g1 : g0); }

// ---------------- small kernels ----------------
__global__ void zero_kernel(float* p, int n) {
    int i = blockIdx.x * blockDim.x + threadIdx.x;
    if (i < n) p[i] = 0.f;
}

__global__ void build_wghq(const float* __restrict__ dWhh, const float* __restrict__ aWh) {
    int i = blockIdx.x * blockDim.x + threadIdx.x;
    if (i >= H * GHQ) return;
    int r = i >> 10, c = i & (GHQ - 1);
    d_Wghq[i] = (c < H3) ? dWhh[r * H3 + c] : aWh[r * H + (c - H3)];
}
__global__ void build_bghq(const float* __restrict__ dbhh) {
    int i = blockIdx.x * blockDim.x + threadIdx.x;
    if (i >= GHQ) return;
    d_bghq[i] = (i < H3) ? dbhh[i] : 0.f;
}

// encoder GRU gate, both directions; gi gathered from vocab table
__global__ void enc_gate_kernel(const int* __restrict__ src, int t) {
    int i = blockIdx.x * blockDim.x + threadIdx.x;
    if (i >= 2 * B * H) return;
    int dir = i / (B * H);
    int rem = i - dir * (B * H);
    int b = rem / H, j = rem - b * H;

    int srow = dir ? (S - 1 - t) : t;
    int tok  = src[srow * B + b];
    const float* gi = (dir ? d_tabB : d_tabF) + (size_t)tok * H3;
    const float* gh = d_gh2 + ((size_t)dir * B + b) * H3;

    float h  = d_h2[i];
    float r  = sigmoidf(gi[j]         + gh[j]);
    float z  = sigmoidf(gi[j + H]     + gh[j + H]);
    float n  = tanhf  (gi[j + 2 * H] + r * gh[j + 2 * H]);
    float hn = (1.f - z) * n + z * h;
    d_h2[i] = hn;
    d_encbse[((size_t)b * S + srow) * DH + dir * H + j] = hn;
}

__global__ void hcat_kernel() {
    int i = blockIdx.x * blockDim.x + threadIdx.x;
    if (i >= B * DH) return;
    int b = i / DH, j = i - b * DH;
    d_hcat[i] = d_h2[(j < H ? 0 : 1) * B * H + b * H + (j & (H - 1))];
}

// fused attention: energy + softmax + weighted sum. One block per batch row.
__global__ void __launch_bounds__(256) attn_kernel(const float* __restrict__ ab,
                                                   const float* __restrict__ av) {
    const int b   = blockIdx.x;
    const int tid = threadIdx.x;
    __shared__ float qs[H];
    __shared__ float sc[S];
    __shared__ float aw[S];

    qs[tid] = d_ghq[(size_t)b * GHQ + H3 + tid] + ab[tid];
    __syncthreads();

    const int warp = tid >> 5, lane = tid & 31;
    for (int s = warp; s < S; s += 8) {
        const float* ep = d_eproj + ((size_t)b * S + s) * H;
        float acc = 0.f;
        #pragma unroll
        for (int k = lane; k < H; k += 32)
            acc += tanhf(qs[k] + ep[k]) * av[k];
        #pragma unroll
        for (int o = 16; o; o >>= 1) acc += __shfl_down_sync(0xFFFFFFFFu, acc, o);
        if (lane == 0) sc[s] = acc;
    }
    __syncthreads();

    if (tid == 0) {
        float m = sc[0];
        #pragma unroll
        for (int s = 1; s < S; s++) m = fmaxf(m, sc[s]);
        float sum = 0.f;
        #pragma unroll
        for (int s = 0; s < S; s++) { float e = expf(sc[s] - m); aw[s] = e; sum += e; }
        float inv = 1.f / sum;
        #pragma unroll
        for (int s = 0; s < S; s++) aw[s] *= inv;
    }
    __syncthreads();

    for (int d = tid; d < DH; d += 256) {
        const float* eb = d_encbse + (size_t)b * S * DH + d;
        float w = 0.f;
        #pragma unroll
        for (int s = 0; s < S; s++) w += aw[s] * eb[s * DH];
        d_w  [b * DH + d]       = w;
        d_cat[b * CATK + H + d] = w;
    }
}

__global__ void dec_gate_kernel() {
    int i = blockIdx.x * blockDim.x + threadIdx.x;
    if (i >= B * H) return;
    int b = i / H, j = i - b * H;
    const float* gi = d_gi  + (size_t)b * H3;
    const float* gh = d_ghq + (size_t)b * GHQ;
    float h  = d_hid[i];
    float r  = sigmoidf(gi[j]         + gh[j]);
    float z  = sigmoidf(gi[j + H]     + gh[j + H]);
    float n  = tanhf  (gi[j + 2 * H] + r * gh[j + 2 * H]);
    float hn = (1.f - z) * n + z * h;
    d_hid[i] = hn;
    d_cat[b * CATK + j] = hn;
}

// ---------------- host ----------------
static float* sym_addr(const void* symbol) {
    void* p = nullptr;
    cudaGetSymbolAddress(&p, symbol);
    return (float*)p;
}
static inline int cdiv(int a, int b) { return (a + b - 1) / b; }

static void launch1(const GA& g) {
    dim3 gr(cdiv(g.N, 64), cdiv(g.M, 128));
    gemm1<<<gr, 256>>>(g);
}
static void launch2(const GA& g0, const GA& g1) {
    dim3 gr(max(cdiv(g0.N, 64), cdiv(g1.N, 64)),
            max(cdiv(g0.M, 128), cdiv(g1.M, 128)), 2);
    gemm2<<<gr, 256>>>(g0, g1);
}

extern "C" void kernel_launch(void* const* d_in, const int* in_sizes, int n_in,
                              void* d_out, int out_size) {
    const int*   src    = (const int*)  d_in[0];
    const int*   trg    = (const int*)  d_in[1];
    const float* eemb   = (const float*)d_in[2];
    const float* Wih_f  = (const float*)d_in[3];
    const float* Whh_f  = (const float*)d_in[4];
    const float* bih_f  = (const float*)d_in[5];
    const float* bhh_f  = (const float*)d_in[6];
    const float* Wih_b  = (const float*)d_in[7];
    const float* Whh_b  = (const float*)d_in[8];
    const float* bih_b  = (const float*)d_in[9];
    const float* bhh_b  = (const float*)d_in[10];
    const float* efcW   = (const float*)d_in[11];
    const float* efcb   = (const float*)d_in[12];
    const float* aWh    = (const float*)d_in[13];
    const float* aWe    = (const float*)d_in[14];
    const float* ab     = (const float*)d_in[15];
    const float* av     = (const float*)d_in[16];
    const float* demb   = (const float*)d_in[17];
    const float* dWih   = (const float*)d_in[18];
    const float* dWhh   = (const float*)d_in[19];
    const float* dbih   = (const float*)d_in[20];
    const float* dbhh   = (const float*)d_in[21];
    const float* fcW    = (const float*)d_in[22];
    const float* fcb    = (const float*)d_in[23];
    float* out = (float*)d_out;

    float* ptabF   = sym_addr(d_tabF);
    float* ptabB   = sym_addr(d_tabB);
    float* ptabGi  = sym_addr(d_tabGi);
    float* ptabLg  = sym_addr(d_tabLg);
    float* ph2     = sym_addr(d_h2);
    float* pgh2    = sym_addr(d_gh2);
    float* pencbse = sym_addr(d_encbse);
    float* phcat   = sym_addr(d_hcat);
    float* phid    = sym_addr(d_hid);
    float* peproj  = sym_addr(d_eproj);
    float* pw      = sym_addr(d_w);
    float* pcat    = sym_addr(d_cat);
    float* pgi     = sym_addr(d_gi);
    float* pghq    = sym_addr(d_ghq);
    float* pWghq   = sym_addr(d_Wghq);
    float* pbghq   = sym_addr(d_bghq);

    // init
    zero_kernel<<<cdiv(2 * B * H, 256), 256>>>(ph2, 2 * B * H);
    zero_kernel<<<cdiv(B * VOUTD, 256), 256>>>(out, B * VOUTD);

    // vocab tables + fused decoder weights
    launch2(GA{eemb, Wih_f, bih_f, nullptr, nullptr, ptabF, VIN, H3, E, 0},
            GA{eemb, Wih_b, bih_b, nullptr, nullptr, ptabB, VIN, H3, E, 0});
    launch2(GA{demb, dWih, nullptr, nullptr, nullptr, ptabGi, VOUTD, H3, E, 0},
            GA{demb, fcW + (size_t)(H + DH) * VOUTD, nullptr, nullptr, nullptr,
               ptabLg, VOUTD, VOUTD, E, 0});
    build_wghq<<<cdiv(H * GHQ, 256), 256>>>(dWhh, aWh);
    build_bghq<<<cdiv(GHQ, 256), 256>>>(dbhh);

    // encoder recurrent scan (fwd + bwd fused)
    for (int t = 0; t < S; t++) {
        launch2(GA{ph2,          Whh_f, bhh_f, nullptr, nullptr, pgh2,          B, H3, H, 0},
                GA{ph2 + B * H,  Whh_b, bhh_b, nullptr, nullptr, pgh2 + B * H3, B, H3, H, 0});
        enc_gate_kernel<<<cdiv(2 * B * H, 256), 256>>>(src, t);
    }

    // decoder initial hidden + enc_proj + first ghq
    hcat_kernel<<<cdiv(B * DH, 256), 256>>>();
    launch1(GA{phcat, efcW, efcb, nullptr, nullptr, phid, B, H, DH, 1});
    launch1(GA{pencbse, aWe, nullptr, nullptr, nullptr, peproj, B * S, H, DH, 0});
    launch1(GA{phid, pWghq, pbghq, nullptr, nullptr, pghq, B, GHQ, H, 0});

    // decoder scan
    for (int t = 0; t < T - 1; t++) {
        attn_kernel<<<B, 256>>>(ab, av);
        // gi = weighted @ dWih[E:] + bih + tabGi[trg_t]
        launch1(GA{pw, dWih + (size_t)E * H3, dbih, ptabGi, trg + t * B, pgi, B, H3, DH, 0});
        dec_gate_kernel<<<cdiv(B * H, 256), 256>>>();
        // logits(t) fused with ghq(t+1): both depend only on gate(t)
        launch2(GA{pcat, fcW, fcb, ptabLg, trg + t * B,
                   out + (size_t)(t + 1) * B * VOUTD, B, VOUTD, CATK, 0},
                GA{phid, pWghq, pbghq, nullptr, nullptr, pghq, B, GHQ, H, 0});
    }
}

// round 11
// speedup vs baseline: 2.6803x; 1.8464x over previous
#include <cuda_runtime.h>
#include <cstdint>

// ---------------- problem constants ----------------
constexpr int B    = 2048;
constexpr int S    = 24;
constexpr int T    = 25;
constexpr int H    = 256;
constexpr int E    = 300;
constexpr int VIN  = 300;
constexpr int VOUTD= 128;
constexpr int H3   = 3 * H;      // 768
constexpr int DH   = 2 * H;      // 512
constexpr int CATK = H + DH;     // 768 (hn | weighted)
constexpr int GHQ  = H3 + H;     // 1024 (gh | q)

// ---------------- scratch (static device, no allocation) ----------------
__device__ float d_tabF [VIN * H3];          // emb @ Wih_f + bih_f
__device__ float d_tabB [VIN * H3];
__device__ float d_tabGi[VOUTD * H3];        // dec_emb @ dec_Wih[0:E]
__device__ float d_tabLg[VOUTD * VOUTD];     // dec_emb @ fcW[H+2H:]
__device__ float d_h2   [2 * B * H];         // fwd/bwd encoder hidden
__device__ float d_gh2  [2 * B * H3];        // h @ Whh (+bhh)
__device__ float d_encbse[B * S * DH];       // (B,S,2H)
__device__ float d_hcat [B * DH];
__device__ float d_hid  [B * H];             // decoder hidden
__device__ float d_eproj[B * S * H];
__device__ float d_w    [B * DH];            // attention-weighted context
__device__ float d_cat  [B * CATK];          // [hn | weighted]
__device__ float d_gi   [B * H3];
__device__ float d_ghq  [B * GHQ];           // [gh(768) | q(256)]
__device__ float d_Wghq [H * GHQ];           // [dWhh | attn_Wh]
__device__ float d_bghq [GHQ];               // [dbhh | 0]

__device__ __forceinline__ float sigmoidf(float x) { return 1.f / (1.f + expf(-x)); }

// ---------------- TF32 tensor-core GEMM ----------------
struct GA {
    const float* A;     // M x K (lda=K)
    const float* W;     // K x N (ldb=N)
    const float* bias;  // N or null
    const float* gadd;  // gather-add table (rows of width N) or null
    const int*   gidx;  // per-row index or null
    float*       C;     // M x N
    int M, N, K;
    int act;            // 0 none, 1 tanh
};

constexpr int GBM = 128, GBN = 64, GBK = 32;
constexpr int AS_STRIDE = GBK + 4;                 // 36 (a-frag banks = (4*fr+fc)%32, conflict-free)
constexpr int BS_STRIDE = GBN + 8;                 // 72 (b-frag banks = (8*fc+fr)%32, conflict-free)
constexpr int AS_SIZE   = GBM * AS_STRIDE;         // u32 count
constexpr int BS_SIZE   = GBK * BS_STRIDE;
constexpr int GEMM_SMEM = 2 * (AS_SIZE + BS_SIZE) * 4;  // 55296 B (needs attribute)

__device__ __forceinline__ uint32_t f2tf(float x) {
    uint32_t u; asm("cvt.rna.tf32.f32 %0, %1;" : "=r"(u) : "f"(x)); return u;
}

__device__ __forceinline__ void mma8(float* c, const uint32_t* a, const uint32_t* b) {
    asm volatile(
        "mma.sync.aligned.m16n8k8.row.col.f32.tf32.tf32.f32 "
        "{%0,%1,%2,%3}, {%4,%5,%6,%7}, {%8,%9}, {%0,%1,%2,%3};"
        : "+f"(c[0]), "+f"(c[1]), "+f"(c[2]), "+f"(c[3])
        : "r"(a[0]), "r"(a[1]), "r"(a[2]), "r"(a[3]), "r"(b[0]), "r"(b[1]));
}

__device__ __forceinline__ void gemm_body(const GA g) {
    extern __shared__ uint32_t smbuf[];
    uint32_t* As = smbuf;                 // [2][GBM][AS_STRIDE]
    uint32_t* Bs = smbuf + 2 * AS_SIZE;   // [2][GBK][BS_STRIDE]

    const int tid  = threadIdx.x;
    const int row0 = blockIdx.y * GBM;
    const int col0 = blockIdx.x * GBN;
    if (row0 >= g.M || col0 >= g.N) return;

    const int lane = tid & 31, warp = tid >> 5;
    const int wm = (warp >> 1) * 32;     // 4 warps along M
    const int wn = (warp & 1) * 32;      // 2 warps along N
    const int fr = lane >> 2;            // 0..7
    const int fc = lane & 3;             // 0..3

    const int nk = (g.K + GBK - 1) / GBK;

    float4 pa[4], pb[2];

    auto loadA = [&](int kt) {
        const int k0 = kt * GBK;
        #pragma unroll
        for (int i = 0; i < 4; i++) {
            int idx = tid + i * 256;
            int rr = idx >> 3, c4 = (idx & 7) * 4;
            int gr = row0 + rr, gc = k0 + c4;
            pa[i] = (gr < g.M && gc < g.K)   // all K are multiples of 4
                  ? *reinterpret_cast<const float4*>(&g.A[(size_t)gr * g.K + gc])
                  : make_float4(0.f, 0.f, 0.f, 0.f);
        }
    };
    auto loadB = [&](int kt) {
        const int k0 = kt * GBK;
        #pragma unroll
        for (int i = 0; i < 2; i++) {
            int idx = tid + i * 256;
            int rr = idx >> 4, c4 = (idx & 15) * 4;
            int gr = k0 + rr;
            pb[i] = (gr < g.K)
                  ? *reinterpret_cast<const float4*>(&g.W[(size_t)gr * g.N + col0 + c4])
                  : make_float4(0.f, 0.f, 0.f, 0.f);
        }
    };
    auto stage = [&](int buf) {
        uint32_t* A  = As + buf * AS_SIZE;
        uint32_t* Bb = Bs + buf * BS_SIZE;
        #pragma unroll
        for (int i = 0; i < 4; i++) {
            int idx = tid + i * 256;
            int rr = idx >> 3, c4 = (idx & 7) * 4;
            uint4 v = make_uint4(f2tf(pa[i].x), f2tf(pa[i].y), f2tf(pa[i].z), f2tf(pa[i].w));
            *reinterpret_cast<uint4*>(&A[rr * AS_STRIDE + c4]) = v;
        }
        #pragma unroll
        for (int i = 0; i < 2; i++) {
            int idx = tid + i * 256;
            int rr = idx >> 4, c4 = (idx & 15) * 4;
            uint4 v = make_uint4(f2tf(pb[i].x), f2tf(pb[i].y), f2tf(pb[i].z), f2tf(pb[i].w));
            *reinterpret_cast<uint4*>(&Bb[rr * BS_STRIDE + c4]) = v;
        }
    };

    float acc[2][4][4] = {};

    loadA(0); loadB(0); stage(0); __syncthreads();

    for (int kt = 0; kt < nk; kt++) {
        const int cur = kt & 1;
        if (kt + 1 < nk) { loadA(kt + 1); loadB(kt + 1); }
        const uint32_t* A  = As + cur * AS_SIZE;
        const uint32_t* Bb = Bs + cur * BS_SIZE;
        #pragma unroll
        for (int ks = 0; ks < 4; ks++) {
            const int k8 = ks * 8;
            uint32_t af[2][4], bf[4][2];
            #pragma unroll
            for (int i = 0; i < 2; i++) {
                const uint32_t* ap = &A[(wm + i * 16 + fr) * AS_STRIDE + k8 + fc];
                af[i][0] = ap[0];
                af[i][1] = ap[8 * AS_STRIDE];
                af[i][2] = ap[4];
                af[i][3] = ap[8 * AS_STRIDE + 4];
            }
            #pragma unroll
            for (int j = 0; j < 4; j++) {
                const uint32_t* bp = &Bb[(k8 + fc) * BS_STRIDE + wn + j * 8 + fr];
                bf[j][0] = bp[0];
                bf[j][1] = bp[4 * BS_STRIDE];
            }
            #pragma unroll
            for (int i = 0; i < 2; i++)
                #pragma unroll
                for (int j = 0; j < 4; j++)
                    mma8(acc[i][j], af[i], bf[j]);
        }
        if (kt + 1 < nk) { stage(cur ^ 1); __syncthreads(); }
    }

    // epilogue: bias + gather-add + optional tanh
    #pragma unroll
    for (int i = 0; i < 2; i++) {
        #pragma unroll
        for (int half = 0; half < 2; half++) {
            const int r = row0 + wm + i * 16 + fr + half * 8;
            if (r >= g.M) continue;
            const float* grow = g.gidx ? &g.gadd[(size_t)g.gidx[r] * g.N] : nullptr;
            #pragma unroll
            for (int j = 0; j < 4; j++) {
                const int c = col0 + wn + j * 8 + fc * 2;
                float v0 = acc[i][j][half * 2 + 0];
                float v1 = acc[i][j][half * 2 + 1];
                if (g.bias) { v0 += g.bias[c]; v1 += g.bias[c + 1]; }
                if (grow)   { v0 += grow[c];   v1 += grow[c + 1];   }
                if (g.act == 1) { v0 = tanhf(v0); v1 = tanhf(v1); }
                *reinterpret_cast<float2*>(&g.C[(size_t)r * g.N + c]) = make_float2(v0, v1);
            }
        }
    }
}

__global__ void __launch_bounds__(256) gemm1(GA g)         { gemm_body(g); }
__global__ void __launch_bounds__(256) gemm2(GA g0, GA g1) { gemm_body(blockIdx.z ? g1 : g0); }

// ---------------- small kernels ----------------
__global__ void zero_kernel(float* p, int n) {
    int i = blockIdx.x * blockDim.x + threadIdx.x;
    if (i < n) p[i] = 0.f;
}

__global__ void build_wghq(const float* __restrict__ dWhh, const float* __restrict__ aWh) {
    int i = blockIdx.x * blockDim.x + threadIdx.x;
    if (i >= H * GHQ) return;
    int r = i >> 10, c = i & (GHQ - 1);
    d_Wghq[i] = (c < H3) ? dWhh[r * H3 + c] : aWh[r * H + (c - H3)];
}
__global__ void build_bghq(const float* __restrict__ dbhh) {
    int i = blockIdx.x * blockDim.x + threadIdx.x;
    if (i >= GHQ) return;
    d_bghq[i] = (i < H3) ? dbhh[i] : 0.f;
}

// encoder GRU gate, both directions; gi gathered from vocab table
__global__ void enc_gate_kernel(const int* __restrict__ src, int t) {
    int i = blockIdx.x * blockDim.x + threadIdx.x;
    if (i >= 2 * B * H) return;
    int dir = i / (B * H);
    int rem = i - dir * (B * H);
    int b = rem / H, j = rem - b * H;

    int srow = dir ? (S - 1 - t) : t;
    int tok  = src[srow * B + b];
    const float* gi = (dir ? d_tabB : d_tabF) + (size_t)tok * H3;
    const float* gh = d_gh2 + ((size_t)dir * B + b) * H3;

    float h  = d_h2[i];
    float r  = sigmoidf(gi[j]         + gh[j]);
    float z  = sigmoidf(gi[j + H]     + gh[j + H]);
    float n  = tanhf  (gi[j + 2 * H] + r * gh[j + 2 * H]);
    float hn = (1.f - z) * n + z * h;
    d_h2[i] = hn;
    d_encbse[((size_t)b * S + srow) * DH + dir * H + j] = hn;
}

__global__ void hcat_kernel() {
    int i = blockIdx.x * blockDim.x + threadIdx.x;
    if (i >= B * DH) return;
    int b = i / DH, j = i - b * DH;
    d_hcat[i] = d_h2[(j < H ? 0 : 1) * B * H + b * H + (j & (H - 1))];
}

// fused attention: energy + softmax + weighted sum. One block per batch row.
__global__ void __launch_bounds__(256) attn_kernel(const float* __restrict__ ab,
                                                   const float* __restrict__ av) {
    const int b   = blockIdx.x;
    const int tid = threadIdx.x;
    __shared__ float qs[H];
    __shared__ float sc[S];
    __shared__ float aw[S];

    qs[tid] = d_ghq[(size_t)b * GHQ + H3 + tid] + ab[tid];
    __syncthreads();

    const int warp = tid >> 5, lane = tid & 31;
    for (int s = warp; s < S; s += 8) {
        const float* ep = d_eproj + ((size_t)b * S + s) * H;
        float acc = 0.f;
        #pragma unroll
        for (int k = lane; k < H; k += 32)
            acc += tanhf(qs[k] + ep[k]) * av[k];
        #pragma unroll
        for (int o = 16; o; o >>= 1) acc += __shfl_down_sync(0xFFFFFFFFu, acc, o);
        if (lane == 0) sc[s] = acc;
    }
    __syncthreads();

    if (tid == 0) {
        float m = sc[0];
        #pragma unroll
        for (int s = 1; s < S; s++) m = fmaxf(m, sc[s]);
        float sum = 0.f;
        #pragma unroll
        for (int s = 0; s < S; s++) { float e = expf(sc[s] - m); aw[s] = e; sum += e; }
        float inv = 1.f / sum;
        #pragma unroll
        for (int s = 0; s < S; s++) aw[s] *= inv;
    }
    __syncthreads();

    for (int d = tid; d < DH; d += 256) {
        const float* eb = d_encbse + (size_t)b * S * DH + d;
        float w = 0.f;
        #pragma unroll
        for (int s = 0; s < S; s++) w += aw[s] * eb[s * DH];
        d_w  [b * DH + d]       = w;
        d_cat[b * CATK + H + d] = w;
    }
}

__global__ void dec_gate_kernel() {
    int i = blockIdx.x * blockDim.x + threadIdx.x;
    if (i >= B * H) return;
    int b = i / H, j = i - b * H;
    const float* gi = d_gi  + (size_t)b * H3;
    const float* gh = d_ghq + (size_t)b * GHQ;
    float h  = d_hid[i];
    float r  = sigmoidf(gi[j]         + gh[j]);
    float z  = sigmoidf(gi[j + H]     + gh[j + H]);
    float n  = tanhf  (gi[j + 2 * H] + r * gh[j + 2 * H]);
    float hn = (1.f - z) * n + z * h;
    d_hid[i] = hn;
    d_cat[b * CATK + j] = hn;
}

// ---------------- host ----------------
static float* sym_addr(const void* symbol) {
    void* p = nullptr;
    cudaGetSymbolAddress(&p, symbol);
    return (float*)p;
}
static inline int cdiv(int a, int b) { return (a + b - 1) / b; }

static void launch1(const GA& g) {
    dim3 gr(cdiv(g.N, GBN), cdiv(g.M, GBM));
    gemm1<<<gr, 256, GEMM_SMEM>>>(g);
}
static void launch2(const GA& g0, const GA& g1) {
    dim3 gr(max(cdiv(g0.N, GBN), cdiv(g1.N, GBN)),
            max(cdiv(g0.M, GBM), cdiv(g1.M, GBM)), 2);
    gemm2<<<gr, 256, GEMM_SMEM>>>(g0, g1);
}

extern "C" void kernel_launch(void* const* d_in, const int* in_sizes, int n_in,
                              void* d_out, int out_size) {
    const int*   src    = (const int*)  d_in[0];
    const int*   trg    = (const int*)  d_in[1];
    const float* eemb   = (const float*)d_in[2];
    const float* Wih_f  = (const float*)d_in[3];
    const float* Whh_f  = (const float*)d_in[4];
    const float* bih_f  = (const float*)d_in[5];
    const float* bhh_f  = (const float*)d_in[6];
    const float* Wih_b  = (const float*)d_in[7];
    const float* Whh_b  = (const float*)d_in[8];
    const float* bih_b  = (const float*)d_in[9];
    const float* bhh_b  = (const float*)d_in[10];
    const float* efcW   = (const float*)d_in[11];
    const float* efcb   = (const float*)d_in[12];
    const float* aWh    = (const float*)d_in[13];
    const float* aWe    = (const float*)d_in[14];
    const float* ab     = (const float*)d_in[15];
    const float* av     = (const float*)d_in[16];
    const float* demb   = (const float*)d_in[17];
    const float* dWih   = (const float*)d_in[18];
    const float* dWhh   = (const float*)d_in[19];
    const float* dbih   = (const float*)d_in[20];
    const float* dbhh   = (const float*)d_in[21];
    const float* fcW    = (const float*)d_in[22];
    const float* fcb    = (const float*)d_in[23];
    float* out = (float*)d_out;

    // allow 55.3 KB dynamic smem on the GEMM kernels (no-op after first call)
    cudaFuncSetAttribute(gemm1, cudaFuncAttributeMaxDynamicSharedMemorySize, GEMM_SMEM);
    cudaFuncSetAttribute(gemm2, cudaFuncAttributeMaxDynamicSharedMemorySize, GEMM_SMEM);

    float* ptabF   = sym_addr(d_tabF);
    float* ptabB   = sym_addr(d_tabB);
    float* ptabGi  = sym_addr(d_tabGi);
    float* ptabLg  = sym_addr(d_tabLg);
    float* ph2     = sym_addr(d_h2);
    float* pgh2    = sym_addr(d_gh2);
    float* pencbse = sym_addr(d_encbse);
    float* phcat   = sym_addr(d_hcat);
    float* phid    = sym_addr(d_hid);
    float* peproj  = sym_addr(d_eproj);
    float* pw      = sym_addr(d_w);
    float* pcat    = sym_addr(d_cat);
    float* pgi     = sym_addr(d_gi);
    float* pghq    = sym_addr(d_ghq);
    float* pWghq   = sym_addr(d_Wghq);
    float* pbghq   = sym_addr(d_bghq);

    // init
    zero_kernel<<<cdiv(2 * B * H, 256), 256>>>(ph2, 2 * B * H);
    zero_kernel<<<cdiv(B * VOUTD, 256), 256>>>(out, B * VOUTD);

    // vocab tables + fused decoder weights
    launch2(GA{eemb, Wih_f, bih_f, nullptr, nullptr, ptabF, VIN, H3, E, 0},
            GA{eemb, Wih_b, bih_b, nullptr, nullptr, ptabB, VIN, H3, E, 0});
    launch2(GA{demb, dWih, nullptr, nullptr, nullptr, ptabGi, VOUTD, H3, E, 0},
            GA{demb, fcW + (size_t)(H + DH) * VOUTD, nullptr, nullptr, nullptr,
               ptabLg, VOUTD, VOUTD, E, 0});
    build_wghq<<<cdiv(H * GHQ, 256), 256>>>(dWhh, aWh);
    build_bghq<<<cdiv(GHQ, 256), 256>>>(dbhh);

    // encoder recurrent scan (fwd + bwd fused)
    for (int t = 0; t < S; t++) {
        launch2(GA{ph2,          Whh_f, bhh_f, nullptr, nullptr, pgh2,          B, H3, H, 0},
                GA{ph2 + B * H,  Whh_b, bhh_b, nullptr, nullptr, pgh2 + B * H3, B, H3, H, 0});
        enc_gate_kernel<<<cdiv(2 * B * H, 256), 256>>>(src, t);
    }

    // decoder initial hidden + enc_proj + first ghq
    hcat_kernel<<<cdiv(B * DH, 256), 256>>>();
    launch1(GA{phcat, efcW, efcb, nullptr, nullptr, phid, B, H, DH, 1});
    launch1(GA{pencbse, aWe, nullptr, nullptr, nullptr, peproj, B * S, H, DH, 0});
    launch1(GA{phid, pWghq, pbghq, nullptr, nullptr, pghq, B, GHQ, H, 0});

    // decoder scan
    for (int t = 0; t < T - 1; t++) {
        attn_kernel<<<B, 256>>>(ab, av);
        // gi = weighted @ dWih[E:] + bih + tabGi[trg_t]
        launch1(GA{pw, dWih + (size_t)E * H3, dbih, ptabGi, trg + t * B, pgi, B, H3, DH, 0});
        dec_gate_kernel<<<cdiv(B * H, 256), 256>>>();
        // logits(t) fused with ghq(t+1): both depend only on gate(t)
        launch2(GA{pcat, fcW, fcb, ptabLg, trg + t * B,
                   out + (size_t)(t + 1) * B * VOUTD, B, VOUTD, CATK, 0},
                GA{phid, pWghq, pbghq, nullptr, nullptr, pghq, B, GHQ, H, 0});
    }
}

// round 16
// speedup vs baseline: 3.8792x; 1.4473x over previous
#include <cuda_runtime.h>
#include <cuda_fp16.h>
#include <cstdint>

// ---------------- problem constants ----------------
constexpr int B    = 2048;
constexpr int S    = 24;
constexpr int T    = 25;
constexpr int H    = 256;
constexpr int E    = 300;
constexpr int VIN  = 300;
constexpr int VOUTD= 128;
constexpr int H3   = 3 * H;      // 768
constexpr int DH   = 2 * H;      // 512
constexpr int GHQ  = H3 + H;     // 1024 (gh | q)
constexpr int NBIG = VOUTD + GHQ;// 1152 fused decoder GEMM width

// ---------------- scratch (static device, no allocation) ----------------
__device__ float d_tabF [VIN * H3];
__device__ float d_tabB [VIN * H3];
__device__ float d_tabGi[VOUTD * H3];
__device__ float d_tabLg[VOUTD * VOUTD];
__device__ float d_h2   [2 * B * H];
__device__ float d_gh2  [2 * B * H3];
__device__ float d_encbse[B * S * DH];
__device__ __half d_encbse_h[B * S * DH];
__device__ float d_hcat [B * DH];
__device__ float d_hid  [B * H];
__device__ float d_eproj[B * S * H];
__device__ __half d_eproj_h[B * S * H];
__device__ float d_w    [B * DH];
__device__ float d_wlg  [B * VOUTD];         // weighted @ fcW[256:768]
__device__ float d_gi   [B * H3];
__device__ float d_ghq  [B * GHQ];           // [gh(768) | q(256)]
__device__ float d_WBIG [H * NBIG];          // [fcW(0:256) | dWhh | attn_Wh]
__device__ float d_bBIG [NBIG];              // [fcb | dbhh | 0]

__device__ __forceinline__ float sigmoidf(float x) { return 1.f / (1.f + expf(-x)); }
__device__ __forceinline__ float tanh_fast(float x) {
    float y; asm("tanh.approx.f32 %0, %1;" : "=f"(y) : "f"(x)); return y;
}

// ---------------- TF32 tensor-core GEMM ----------------
struct GA {
    const float* A;     // M x K (lda=K)
    const float* W;     // K x N (ldb=ldw)
    const float* bias;  // N or null
    const float* gadd;  // gather-add table or null (row stride: N for act!=2, VOUTD for act==2)
    const int*   gidx;  // per-row index or null
    float*       C;     // output (act!=2: M x N; act==2: ghq region M x 1024)
    int M, N, K, ldw;
    int act;            // 0 none, 1 tanh, 2 fused-decoder epilogue
    const float* add0;  // act==2: per-row add for cols<128 (M x 128)
    float*       C2;    // act==2: logits out (M x 128)
};

constexpr int GBM = 128, GBN = 64, GBK = 32;
constexpr int AS_STRIDE = GBK + 4;
constexpr int BS_STRIDE = GBN + 8;
constexpr int AS_SIZE   = GBM * AS_STRIDE;
constexpr int BS_SIZE   = GBK * BS_STRIDE;
constexpr int GEMM_SMEM = 2 * (AS_SIZE + BS_SIZE) * 4;  // 55296 B

__device__ __forceinline__ uint32_t f2tf(float x) {
    uint32_t u; asm("cvt.rna.tf32.f32 %0, %1;" : "=r"(u) : "f"(x)); return u;
}

__device__ __forceinline__ void mma8(float* c, const uint32_t* a, const uint32_t* b) {
    asm volatile(
        "mma.sync.aligned.m16n8k8.row.col.f32.tf32.tf32.f32 "
        "{%0,%1,%2,%3}, {%4,%5,%6,%7}, {%8,%9}, {%0,%1,%2,%3};"
        : "+f"(c[0]), "+f"(c[1]), "+f"(c[2]), "+f"(c[3])
        : "r"(a[0]), "r"(a[1]), "r"(a[2]), "r"(a[3]), "r"(b[0]), "r"(b[1]));
}

__device__ __forceinline__ void gemm_body(const GA g) {
    extern __shared__ uint32_t smbuf[];
    uint32_t* As = smbuf;
    uint32_t* Bs = smbuf + 2 * AS_SIZE;

    const int tid  = threadIdx.x;
    const int row0 = blockIdx.y * GBM;
    const int col0 = blockIdx.x * GBN;
    if (row0 >= g.M || col0 >= g.N) return;

    const int lane = tid & 31, warp = tid >> 5;
    const int wm = (warp >> 1) * 32;
    const int wn = (warp & 1) * 32;
    const int fr = lane >> 2;
    const int fc = lane & 3;

    const int nk = (g.K + GBK - 1) / GBK;
    float4 pa[4], pb[2];

    auto loadA = [&](int kt) {
        const int k0 = kt * GBK;
        #pragma unroll
        for (int i = 0; i < 4; i++) {
            int idx = tid + i * 256;
            int rr = idx >> 3, c4 = (idx & 7) * 4;
            int gr = row0 + rr, gc = k0 + c4;
            pa[i] = (gr < g.M && gc < g.K)
                  ? *reinterpret_cast<const float4*>(&g.A[(size_t)gr * g.K + gc])
                  : make_float4(0.f, 0.f, 0.f, 0.f);
        }
    };
    auto loadB = [&](int kt) {
        const int k0 = kt * GBK;
        #pragma unroll
        for (int i = 0; i < 2; i++) {
            int idx = tid + i * 256;
            int rr = idx >> 4, c4 = (idx & 15) * 4;
            int gr = k0 + rr;
            pb[i] = (gr < g.K)
                  ? *reinterpret_cast<const float4*>(&g.W[(size_t)gr * g.ldw + col0 + c4])
                  : make_float4(0.f, 0.f, 0.f, 0.f);
        }
    };
    auto stage = [&](int buf) {
        uint32_t* A  = As + buf * AS_SIZE;
        uint32_t* Bb = Bs + buf * BS_SIZE;
        #pragma unroll
        for (int i = 0; i < 4; i++) {
            int idx = tid + i * 256;
            int rr = idx >> 3, c4 = (idx & 7) * 4;
            uint4 v = make_uint4(f2tf(pa[i].x), f2tf(pa[i].y), f2tf(pa[i].z), f2tf(pa[i].w));
            *reinterpret_cast<uint4*>(&A[rr * AS_STRIDE + c4]) = v;
        }
        #pragma unroll
        for (int i = 0; i < 2; i++) {
            int idx = tid + i * 256;
            int rr = idx >> 4, c4 = (idx & 15) * 4;
            uint4 v = make_uint4(f2tf(pb[i].x), f2tf(pb[i].y), f2tf(pb[i].z), f2tf(pb[i].w));
            *reinterpret_cast<uint4*>(&Bb[rr * BS_STRIDE + c4]) = v;
        }
    };

    float acc[2][4][4] = {};
    loadA(0); loadB(0); stage(0); __syncthreads();

    for (int kt = 0; kt < nk; kt++) {
        const int cur = kt & 1;
        if (kt + 1 < nk) { loadA(kt + 1); loadB(kt + 1); }
        const uint32_t* A  = As + cur * AS_SIZE;
        const uint32_t* Bb = Bs + cur * BS_SIZE;
        #pragma unroll
        for (int ks = 0; ks < 4; ks++) {
            const int k8 = ks * 8;
            uint32_t af[2][4], bf[4][2];
            #pragma unroll
            for (int i = 0; i < 2; i++) {
                const uint32_t* ap = &A[(wm + i * 16 + fr) * AS_STRIDE + k8 + fc];
                af[i][0] = ap[0];
                af[i][1] = ap[8 * AS_STRIDE];
                af[i][2] = ap[4];
                af[i][3] = ap[8 * AS_STRIDE + 4];
            }
            #pragma unroll
            for (int j = 0; j < 4; j++) {
                const uint32_t* bp = &Bb[(k8 + fc) * BS_STRIDE + wn + j * 8 + fr];
                bf[j][0] = bp[0];
                bf[j][1] = bp[4 * BS_STRIDE];
            }
            #pragma unroll
            for (int i = 0; i < 2; i++)
                #pragma unroll
                for (int j = 0; j < 4; j++)
                    mma8(acc[i][j], af[i], bf[j]);
        }
        if (kt + 1 < nk) { stage(cur ^ 1); __syncthreads(); }
    }

    const bool isLogit = (g.act == 2) && (col0 < VOUTD);
    // gather-table row stride: act==2 gathers into the logits slice (width VOUTD),
    // otherwise the table rows match the GEMM output width N.  <-- round-15 bug fix
    const int gstride = (g.act == 2) ? VOUTD : g.N;
    #pragma unroll
    for (int i = 0; i < 2; i++) {
        #pragma unroll
        for (int half = 0; half < 2; half++) {
            const int r = row0 + wm + i * 16 + fr + half * 8;
            if (r >= g.M) continue;
            const float* grow = nullptr;
            if (g.gidx && (g.act != 2 || isLogit))
                grow = &g.gadd[(size_t)g.gidx[r] * gstride];
            #pragma unroll
            for (int j = 0; j < 4; j++) {
                const int c = col0 + wn + j * 8 + fc * 2;
                float v0 = acc[i][j][half * 2 + 0];
                float v1 = acc[i][j][half * 2 + 1];
                if (g.bias) { v0 += g.bias[c]; v1 += g.bias[c + 1]; }
                if (g.act == 2) {
                    if (isLogit) {
                        v0 += grow[c] + g.add0[(size_t)r * VOUTD + c];
                        v1 += grow[c + 1] + g.add0[(size_t)r * VOUTD + c + 1];
                        *reinterpret_cast<float2*>(&g.C2[(size_t)r * VOUTD + c]) = make_float2(v0, v1);
                    } else {
                        *reinterpret_cast<float2*>(&g.C[(size_t)r * GHQ + (c - VOUTD)]) = make_float2(v0, v1);
                    }
                } else {
                    if (grow) { v0 += grow[c]; v1 += grow[c + 1]; }
                    if (g.act == 1) { v0 = tanhf(v0); v1 = tanhf(v1); }
                    *reinterpret_cast<float2*>(&g.C[(size_t)r * g.N + c]) = make_float2(v0, v1);
                }
            }
        }
    }
}

__global__ void __launch_bounds__(256) gemm1(GA g)         { gemm_body(g); }
__global__ void __launch_bounds__(256) gemm2(GA g0, GA g1) { gemm_body(blockIdx.z ? g1 : g0); }

// ---------------- small kernels ----------------
__global__ void zero_kernel(float* p, int n) {
    int i = blockIdx.x * blockDim.x + threadIdx.x;
    if (i < n) p[i] = 0.f;
}

__global__ void build_wbig(const float* __restrict__ fcW, const float* __restrict__ dWhh,
                           const float* __restrict__ aWh) {
    int i = blockIdx.x * blockDim.x + threadIdx.x;
    if (i >= H * NBIG) return;
    int r = i / NBIG, c = i - r * NBIG;
    float v;
    if (c < VOUTD)            v = fcW [r * VOUTD + c];
    else if (c < VOUTD + H3)  v = dWhh[r * H3 + (c - VOUTD)];
    else                      v = aWh [r * H + (c - VOUTD - H3)];
    d_WBIG[i] = v;
}
__global__ void build_bbig(const float* __restrict__ fcb, const float* __restrict__ dbhh) {
    int i = blockIdx.x * blockDim.x + threadIdx.x;
    if (i >= NBIG) return;
    d_bBIG[i] = (i < VOUTD) ? fcb[i] : (i < VOUTD + H3 ? dbhh[i - VOUTD] : 0.f);
}

__global__ void eproj2h_kernel() {
    int i = blockIdx.x * blockDim.x + threadIdx.x;
    if (i < B * S * H) d_eproj_h[i] = __float2half(d_eproj[i]);
}

// encoder GRU gate, both directions; gi gathered from vocab table
__global__ void enc_gate_kernel(const int* __restrict__ src, int t) {
    int i = blockIdx.x * blockDim.x + threadIdx.x;
    if (i >= 2 * B * H) return;
    int dir = i / (B * H);
    int rem = i - dir * (B * H);
    int b = rem / H, j = rem - b * H;

    int srow = dir ? (S - 1 - t) : t;
    int tok  = src[srow * B + b];
    const float* gi = (dir ? d_tabB : d_tabF) + (size_t)tok * H3;
    const float* gh = d_gh2 + ((size_t)dir * B + b) * H3;

    float h  = d_h2[i];
    float r  = sigmoidf(gi[j]         + gh[j]);
    float z  = sigmoidf(gi[j + H]     + gh[j + H]);
    float n  = tanhf  (gi[j + 2 * H] + r * gh[j + 2 * H]);
    float hn = (1.f - z) * n + z * h;
    d_h2[i] = hn;
    size_t oidx = ((size_t)b * S + srow) * DH + dir * H + j;
    d_encbse[oidx]   = hn;
    d_encbse_h[oidx] = __float2half(hn);
}

__global__ void hcat_kernel() {
    int i = blockIdx.x * blockDim.x + threadIdx.x;
    if (i >= B * DH) return;
    int b = i / DH, j = i - b * DH;
    d_hcat[i] = d_h2[(j < H ? 0 : 1) * B * H + b * H + (j & (H - 1))];
}

// fused attention: energy(tanh.approx) + softmax + weighted sum, fp16 inputs.
__global__ void __launch_bounds__(256) attn_kernel(const float* __restrict__ ab,
                                                   const float* __restrict__ av) {
    const int b   = blockIdx.x;
    const int tid = threadIdx.x;
    __shared__ float qs[H], avs[H], sc[S], aw[S];

    qs[tid]  = d_ghq[(size_t)b * GHQ + H3 + tid] + ab[tid];
    avs[tid] = av[tid];
    __syncthreads();

    const int warp = tid >> 5, lane = tid & 31;
    const __half2* eph = reinterpret_cast<const __half2*>(d_eproj_h);
    for (int s = warp; s < S; s += 8) {
        const __half2* ep2 = eph + (size_t)(b * S + s) * (H / 2);
        float acc = 0.f;
        #pragma unroll
        for (int j = lane; j < H / 2; j += 32) {
            float2 f = __half22float2(ep2[j]);
            acc += tanh_fast(qs[2 * j]     + f.x) * avs[2 * j]
                 + tanh_fast(qs[2 * j + 1] + f.y) * avs[2 * j + 1];
        }
        #pragma unroll
        for (int o = 16; o; o >>= 1) acc += __shfl_down_sync(0xFFFFFFFFu, acc, o);
        if (lane == 0) sc[s] = acc;
    }
    __syncthreads();

    if (tid == 0) {
        float m = sc[0];
        #pragma unroll
        for (int s = 1; s < S; s++) m = fmaxf(m, sc[s]);
        float sum = 0.f;
        #pragma unroll
        for (int s = 0; s < S; s++) { float e = expf(sc[s] - m); aw[s] = e; sum += e; }
        float inv = 1.f / sum;
        #pragma unroll
        for (int s = 0; s < S; s++) aw[s] *= inv;
    }
    __syncthreads();

    // weighted context: each thread one half2 column of DH
    const __half2* eb2 = reinterpret_cast<const __half2*>(d_encbse_h)
                       + (size_t)b * S * (DH / 2) + tid;
    float2 w = make_float2(0.f, 0.f);
    #pragma unroll
    for (int s = 0; s < S; s++) {
        float2 e = __half22float2(eb2[(size_t)s * (DH / 2)]);
        w.x += aw[s] * e.x;
        w.y += aw[s] * e.y;
    }
    *reinterpret_cast<float2*>(&d_w[(size_t)b * DH + 2 * tid]) = w;
}

__global__ void dec_gate_kernel() {
    int i = blockIdx.x * blockDim.x + threadIdx.x;
    if (i >= B * H) return;
    int b = i / H, j = i - b * H;
    const float* gi = d_gi  + (size_t)b * H3;
    const float* gh = d_ghq + (size_t)b * GHQ;
    float h  = d_hid[i];
    float r  = sigmoidf(gi[j]         + gh[j]);
    float z  = sigmoidf(gi[j + H]     + gh[j + H]);
    float n  = tanhf  (gi[j + 2 * H] + r * gh[j + 2 * H]);
    d_hid[i] = (1.f - z) * n + z * h;
}

// ---------------- host ----------------
static float* sym_addr(const void* symbol) {
    void* p = nullptr;
    cudaGetSymbolAddress(&p, symbol);
    return (float*)p;
}
static inline int cdiv(int a, int b) { return (a + b - 1) / b; }

static GA mk(const float* A, const float* W, const float* bias, const float* gadd,
             const int* gidx, float* C, int M, int N, int K, int ldw, int act,
             const float* add0 = nullptr, float* C2 = nullptr) {
    GA g; g.A = A; g.W = W; g.bias = bias; g.gadd = gadd; g.gidx = gidx;
    g.C = C; g.M = M; g.N = N; g.K = K; g.ldw = ldw; g.act = act;
    g.add0 = add0; g.C2 = C2; return g;
}

static void launch1(const GA& g) {
    dim3 gr(cdiv(g.N, GBN), cdiv(g.M, GBM));
    gemm1<<<gr, 256, GEMM_SMEM>>>(g);
}
static void launch2(const GA& g0, const GA& g1) {
    dim3 gr(max(cdiv(g0.N, GBN), cdiv(g1.N, GBN)),
            max(cdiv(g0.M, GBM), cdiv(g1.M, GBM)), 2);
    gemm2<<<gr, 256, GEMM_SMEM>>>(g0, g1);
}

extern "C" void kernel_launch(void* const* d_in, const int* in_sizes, int n_in,
                              void* d_out, int out_size) {
    const int*   src    = (const int*)  d_in[0];
    const int*   trg    = (const int*)  d_in[1];
    const float* eemb   = (const float*)d_in[2];
    const float* Wih_f  = (const float*)d_in[3];
    const float* Whh_f  = (const float*)d_in[4];
    const float* bih_f  = (const float*)d_in[5];
    const float* bhh_f  = (const float*)d_in[6];
    const float* Wih_b  = (const float*)d_in[7];
    const float* Whh_b  = (const float*)d_in[8];
    const float* bih_b  = (const float*)d_in[9];
    const float* bhh_b  = (const float*)d_in[10];
    const float* efcW   = (const float*)d_in[11];
    const float* efcb   = (const float*)d_in[12];
    const float* aWh    = (const float*)d_in[13];
    const float* aWe    = (const float*)d_in[14];
    const float* ab     = (const float*)d_in[15];
    const float* av     = (const float*)d_in[16];
    const float* demb   = (const float*)d_in[17];
    const float* dWih   = (const float*)d_in[18];
    const float* dWhh   = (const float*)d_in[19];
    const float* dbih   = (const float*)d_in[20];
    const float* dbhh   = (const float*)d_in[21];
    const float* fcW    = (const float*)d_in[22];
    const float* fcb    = (const float*)d_in[23];
    float* out = (float*)d_out;

    cudaFuncSetAttribute(gemm1, cudaFuncAttributeMaxDynamicSharedMemorySize, GEMM_SMEM);
    cudaFuncSetAttribute(gemm2, cudaFuncAttributeMaxDynamicSharedMemorySize, GEMM_SMEM);

    float* ptabF   = sym_addr(d_tabF);
    float* ptabB   = sym_addr(d_tabB);
    float* ptabGi  = sym_addr(d_tabGi);
    float* ptabLg  = sym_addr(d_tabLg);
    float* ph2     = sym_addr(d_h2);
    float* pgh2    = sym_addr(d_gh2);
    float* pencbse = sym_addr(d_encbse);
    float* phcat   = sym_addr(d_hcat);
    float* phid    = sym_addr(d_hid);
    float* peproj  = sym_addr(d_eproj);
    float* pw      = sym_addr(d_w);
    float* pwlg    = sym_addr(d_wlg);
    float* pgi     = sym_addr(d_gi);
    float* pghq    = sym_addr(d_ghq);
    float* pWBIG   = sym_addr(d_WBIG);
    float* pbBIG   = sym_addr(d_bBIG);

    // init
    zero_kernel<<<cdiv(2 * B * H, 256), 256>>>(ph2, 2 * B * H);
    zero_kernel<<<cdiv(B * VOUTD, 256), 256>>>(out, B * VOUTD);

    // vocab tables + fused decoder weights
    launch2(mk(eemb, Wih_f, bih_f, nullptr, nullptr, ptabF, VIN, H3, E, H3, 0),
            mk(eemb, Wih_b, bih_b, nullptr, nullptr, ptabB, VIN, H3, E, H3, 0));
    launch2(mk(demb, dWih, nullptr, nullptr, nullptr, ptabGi, VOUTD, H3, E, H3, 0),
            mk(demb, fcW + (size_t)(H + DH) * VOUTD, nullptr, nullptr, nullptr,
               ptabLg, VOUTD, VOUTD, E, VOUTD, 0));
    build_wbig<<<cdiv(H * NBIG, 256), 256>>>(fcW, dWhh, aWh);
    build_bbig<<<cdiv(NBIG, 256), 256>>>(fcb, dbhh);

    // encoder recurrent scan (fwd + bwd fused)
    for (int t = 0; t < S; t++) {
        launch2(mk(ph2,         Whh_f, bhh_f, nullptr, nullptr, pgh2,          B, H3, H, H3, 0),
                mk(ph2 + B * H, Whh_b, bhh_b, nullptr, nullptr, pgh2 + B * H3, B, H3, H, H3, 0));
        enc_gate_kernel<<<cdiv(2 * B * H, 256), 256>>>(src, t);
    }

    // decoder initial hidden + enc_proj(+fp16) + first ghq
    hcat_kernel<<<cdiv(B * DH, 256), 256>>>();
    launch1(mk(phcat, efcW, efcb, nullptr, nullptr, phid, B, H, DH, H, 1));
    launch1(mk(pencbse, aWe, nullptr, nullptr, nullptr, peproj, B * S, H, DH, H, 0));
    eproj2h_kernel<<<cdiv(B * S * H, 256), 256>>>();
    launch1(mk(phid, pWBIG + VOUTD, pbBIG + VOUTD, nullptr, nullptr, pghq, B, GHQ, H, NBIG, 0));

    // decoder scan
    for (int t = 0; t < T - 1; t++) {
        attn_kernel<<<B, 256>>>(ab, av);
        // gi = weighted @ dWih[E:] + bih + tabGi[trg_t] ; wlg = weighted @ fcW[256:768]
        launch2(mk(pw, dWih + (size_t)E * H3, dbih, ptabGi, trg + t * B, pgi, B, H3, DH, H3, 0),
                mk(pw, fcW + (size_t)H * VOUTD, nullptr, nullptr, nullptr, pwlg, B, VOUTD, DH, VOUTD, 0));
        dec_gate_kernel<<<cdiv(B * H, 256), 256>>>();
        // fused: [logits | gh | q] = hn @ WBIG ; logits += wlg + fcb + tabLg[trg_t]
        launch1(mk(phid, pWBIG, pbBIG, ptabLg, trg + t * B, pghq, B, NBIG, H, NBIG, 2,
                   pwlg, out + (size_t)(t + 1) * B * VOUTD));
    }
}